// round 2
// baseline (speedup 1.0000x reference)
#include <cuda_runtime.h>
#include <cuda_bf16.h>
#include <stdint.h>

#define N_NODES 50000
#define N_EDGES 800000
#define EDGE_F  96
#define NODE_F  256
#define GLOB_F  64
#define HIDDEN  1024
#define MLP_IN  608   // NODE_F + 3*EDGE_F + GLOB_F

// ---------------- scratch (device globals: allocation-free) ----------------
__device__ float    g_sum[(size_t)N_NODES * EDGE_F];   // segment sum
__device__ unsigned g_maxu[(size_t)N_NODES * EDGE_F];  // segment max (float bits)
__device__ float    g_cnt[N_NODES];                    // segment count
__device__ float    g_H[(size_t)N_NODES * MLP_IN];     // concat MLP input
__device__ float    g_mid[(size_t)N_NODES * HIDDEN];   // hidden activations

// ---------------- init (grid-stride) ----------------
__global__ void init_kernel() {
    const int total = N_NODES * EDGE_F;
    for (int i = blockIdx.x * blockDim.x + threadIdx.x; i < total;
         i += gridDim.x * blockDim.x) {
        g_sum[i]  = 0.0f;
        g_maxu[i] = 0xFF800000u;  // -inf bits
        if (i < N_NODES) g_cnt[i] = 0.0f;
    }
}

// float atomic max via signed-max / unsigned-min split.
// Positive floats compare correctly as signed ints; negative floats compare
// inversely as unsigned ints. Init is -inf (0xFF800000): as int it is very
// negative (any v>=0 wins via signed atomicMax); as uint it is larger than
// any negative float's bits (any v<0 wins via unsigned atomicMin).
__device__ __forceinline__ void atomic_max_f32(unsigned* addr, float v) {
    if (v >= 0.0f) atomicMax((int*)addr, __float_as_int(v));
    else           atomicMin(addr, __float_as_uint(v));
}

// ---------------- scatter: one thread per (edge, 4-feature group) ----------
__global__ void scatter_kernel(const float* __restrict__ edge_attr,
                               const int* __restrict__ col) {
    const int per_edge = EDGE_F / 4;  // 24 float4 groups
    int idx = blockIdx.x * blockDim.x + threadIdx.x;
    if (idx >= N_EDGES * per_edge) return;
    int e  = idx / per_edge;
    int f4 = idx - e * per_edge;
    int c  = col[e];

    float4 v = reinterpret_cast<const float4*>(edge_attr + (size_t)e * EDGE_F)[f4];
    size_t base = (size_t)c * EDGE_F + f4 * 4;

    atomicAdd(&g_sum[base + 0], v.x);
    atomicAdd(&g_sum[base + 1], v.y);
    atomicAdd(&g_sum[base + 2], v.z);
    atomicAdd(&g_sum[base + 3], v.w);

    atomic_max_f32(&g_maxu[base + 0], v.x);
    atomic_max_f32(&g_maxu[base + 1], v.y);
    atomic_max_f32(&g_maxu[base + 2], v.z);
    atomic_max_f32(&g_maxu[base + 3], v.w);

    if (f4 == 0) atomicAdd(&g_cnt[c], 1.0f);
}

// ---------------- assemble concat row [x | sum | max | mean | u[batch]] ----
__global__ void assemble_kernel(const float* __restrict__ x,
                                const float* __restrict__ u,
                                const int* __restrict__ batch) {
    int idx = blockIdx.x * blockDim.x + threadIdx.x;
    const int total = N_NODES * MLP_IN;
    if (idx >= total) return;
    int n = idx / MLP_IN;
    int f = idx - n * MLP_IN;

    float val;
    if (f < NODE_F) {
        val = x[(size_t)n * NODE_F + f];
    } else if (f < NODE_F + EDGE_F) {                    // sum
        val = g_sum[(size_t)n * EDGE_F + (f - NODE_F)];
    } else if (f < NODE_F + 2 * EDGE_F) {                // max (0 if empty)
        float c = g_cnt[n];
        val = (c > 0.0f)
            ? __uint_as_float(g_maxu[(size_t)n * EDGE_F + (f - NODE_F - EDGE_F)])
            : 0.0f;
    } else if (f < NODE_F + 3 * EDGE_F) {                // mean
        float c = g_cnt[n];
        val = g_sum[(size_t)n * EDGE_F + (f - NODE_F - 2 * EDGE_F)] / fmaxf(c, 1.0f);
    } else {                                             // u[batch[n]]
        val = u[(size_t)batch[n] * GLOB_F + (f - NODE_F - 3 * EDGE_F)];
    }
    g_H[idx] = val;
}

// ---------------- SGEMM: C = act(A @ B + bias) [+ resid] -------------------
// A: [M, K] row-major, B: [K, N] row-major, C: [M, N].
// BM=BN=128, BK=16, 256 threads, 8x8 per thread (2x2 float4 quadrants),
// double-buffered shared memory, single __syncthreads per K-tile.
template<bool RELU, bool RESID>
__global__ void __launch_bounds__(256, 2) sgemm_kernel(
    const float* __restrict__ A, const float* __restrict__ B,
    const float* __restrict__ bias, const float* __restrict__ resid,
    float* __restrict__ C, int M, int N, int K)
{
    constexpr int BM = 128, BN = 128, BK = 16;
    __shared__ float As[2][BK][BM];
    __shared__ float Bs[2][BK][BN];

    const int tid = threadIdx.x;
    const int tx = tid & 15;   // 0..15 (column quadrant lane)
    const int ty = tid >> 4;   // 0..15 (row quadrant lane)

    const int blockM = blockIdx.y * BM;
    const int blockN = blockIdx.x * BN;

    // A tile loads: thread -> (row = tid/4 [+64], col4 = (tid%4)*4)
    const int aRow = tid >> 2;          // 0..63
    const int aCol = (tid & 3) * 4;     // 0,4,8,12
    // B tile loads: thread -> (row = tid/32 [+8], col = (tid%32)*4)
    const int bRow = tid >> 5;          // 0..7
    const int bCol = (tid & 31) * 4;    // 0..124

    float acc[8][8];
    #pragma unroll
    for (int i = 0; i < 8; i++)
        #pragma unroll
        for (int j = 0; j < 8; j++) acc[i][j] = 0.0f;

    const int ntiles = K / BK;

    float4 ra[2], rb[2];

    // prologue: fetch tile 0
    #pragma unroll
    for (int s = 0; s < 2; s++) {
        int gr = blockM + aRow + s * 64;
        ra[s] = (gr < M) ? *reinterpret_cast<const float4*>(&A[(size_t)gr * K + aCol])
                         : make_float4(0.f, 0.f, 0.f, 0.f);
        rb[s] = *reinterpret_cast<const float4*>(&B[(size_t)(bRow + s * 8) * N + blockN + bCol]);
    }
    #pragma unroll
    for (int s = 0; s < 2; s++) {
        int r = aRow + s * 64;
        As[0][aCol + 0][r] = ra[s].x;
        As[0][aCol + 1][r] = ra[s].y;
        As[0][aCol + 2][r] = ra[s].z;
        As[0][aCol + 3][r] = ra[s].w;
        *reinterpret_cast<float4*>(&Bs[0][bRow + s * 8][bCol]) = rb[s];
    }
    __syncthreads();

    for (int t = 0; t < ntiles; t++) {
        const int buf = t & 1;

        // fetch next tile into registers (overlaps with compute below)
        if (t + 1 < ntiles) {
            int k0 = (t + 1) * BK;
            #pragma unroll
            for (int s = 0; s < 2; s++) {
                int gr = blockM + aRow + s * 64;
                ra[s] = (gr < M)
                    ? *reinterpret_cast<const float4*>(&A[(size_t)gr * K + k0 + aCol])
                    : make_float4(0.f, 0.f, 0.f, 0.f);
                rb[s] = *reinterpret_cast<const float4*>(
                    &B[(size_t)(k0 + bRow + s * 8) * N + blockN + bCol]);
            }
        }

        // compute on current buffer
        #pragma unroll
        for (int k = 0; k < BK; k++) {
            float4 a0 = *reinterpret_cast<const float4*>(&As[buf][k][ty * 4]);
            float4 a1 = *reinterpret_cast<const float4*>(&As[buf][k][64 + ty * 4]);
            float4 b0 = *reinterpret_cast<const float4*>(&Bs[buf][k][tx * 4]);
            float4 b1 = *reinterpret_cast<const float4*>(&Bs[buf][k][64 + tx * 4]);
            float af[8] = {a0.x, a0.y, a0.z, a0.w, a1.x, a1.y, a1.z, a1.w};
            float bf[8] = {b0.x, b0.y, b0.z, b0.w, b1.x, b1.y, b1.z, b1.w};
            #pragma unroll
            for (int i = 0; i < 8; i++)
                #pragma unroll
                for (int j = 0; j < 8; j++)
                    acc[i][j] = fmaf(af[i], bf[j], acc[i][j]);
        }

        // stage next tile into the other buffer
        if (t + 1 < ntiles) {
            const int nb = buf ^ 1;
            #pragma unroll
            for (int s = 0; s < 2; s++) {
                int r = aRow + s * 64;
                As[nb][aCol + 0][r] = ra[s].x;
                As[nb][aCol + 1][r] = ra[s].y;
                As[nb][aCol + 2][r] = ra[s].z;
                As[nb][aCol + 3][r] = ra[s].w;
                *reinterpret_cast<float4*>(&Bs[nb][bRow + s * 8][bCol]) = rb[s];
            }
        }
        __syncthreads();
    }

    // epilogue: bias (+relu) (+resid), store
    #pragma unroll
    for (int im = 0; im < 2; im++) {
        #pragma unroll
        for (int i = 0; i < 4; i++) {
            int gr = blockM + im * 64 + ty * 4 + i;
            if (gr >= M) continue;
            #pragma unroll
            for (int in = 0; in < 2; in++) {
                int gc = blockN + in * 64 + tx * 4;
                float4 r;
                r.x = acc[im * 4 + i][in * 4 + 0] + bias[gc + 0];
                r.y = acc[im * 4 + i][in * 4 + 1] + bias[gc + 1];
                r.z = acc[im * 4 + i][in * 4 + 2] + bias[gc + 2];
                r.w = acc[im * 4 + i][in * 4 + 3] + bias[gc + 3];
                if (RELU) {
                    r.x = fmaxf(r.x, 0.f); r.y = fmaxf(r.y, 0.f);
                    r.z = fmaxf(r.z, 0.f); r.w = fmaxf(r.w, 0.f);
                }
                if (RESID) {
                    const float4 xr = *reinterpret_cast<const float4*>(
                        &resid[(size_t)gr * N + gc]);
                    r.x += xr.x; r.y += xr.y; r.z += xr.z; r.w += xr.w;
                }
                *reinterpret_cast<float4*>(&C[(size_t)gr * N + gc]) = r;
            }
        }
    }
}

// ---------------- launch ----------------
extern "C" void kernel_launch(void* const* d_in, const int* in_sizes, int n_in,
                              void* d_out, int out_size) {
    const float* x         = (const float*)d_in[0];   // [50000, 256]
    const float* edge_attr = (const float*)d_in[1];   // [800000, 96]
    const float* u         = (const float*)d_in[2];   // [8, 64]
    const float* W1        = (const float*)d_in[3];   // [608, 1024]
    const float* b1        = (const float*)d_in[4];   // [1024]
    const float* W2        = (const float*)d_in[5];   // [1024, 256]
    const float* b2        = (const float*)d_in[6];   // [256]
    const int*   edge_index= (const int*)d_in[7];     // [2, 800000]
    const int*   batch     = (const int*)d_in[8];     // [50000]
    float* out = (float*)d_out;                       // [50000, 256]

    const int* col = edge_index + N_EDGES;  // edge_index[1]

    float *pH = nullptr, *pMid = nullptr;
    cudaGetSymbolAddress((void**)&pH, g_H);
    cudaGetSymbolAddress((void**)&pMid, g_mid);

    // 1) init accumulators
    {
        int total = N_NODES * EDGE_F;
        init_kernel<<<(total + 255) / 256, 256>>>();
    }
    // 2) scatter sum/max/count
    {
        int total = N_EDGES * (EDGE_F / 4);
        scatter_kernel<<<(total + 255) / 256, 256>>>(edge_attr, col);
    }
    // 3) assemble concat input
    {
        int total = N_NODES * MLP_IN;
        assemble_kernel<<<(total + 255) / 256, 256>>>(x, u, batch);
    }
    // 4) GEMM1: mid = relu(H @ W1 + b1)   [50000, 1024]
    {
        dim3 grid(HIDDEN / 128, (N_NODES + 127) / 128);
        sgemm_kernel<true, false><<<grid, 256>>>(pH, W1, b1, nullptr, pMid,
                                                 N_NODES, HIDDEN, MLP_IN);
    }
    // 5) GEMM2: out = mid @ W2 + b2 + x   [50000, 256]
    {
        dim3 grid(NODE_F / 128, (N_NODES + 127) / 128);
        sgemm_kernel<false, true><<<grid, 256>>>(pMid, W2, b2, x, out,
                                                 N_NODES, NODE_F, HIDDEN);
    }
}

// round 6
// speedup vs baseline: 1.5145x; 1.5145x over previous
#include <cuda_runtime.h>
#include <cuda_bf16.h>
#include <stdint.h>

#define N_NODES 50000
#define N_EDGES 800000
#define EDGE_F  96
#define NODE_F  256
#define GLOB_F  64
#define HIDDEN  1024
#define MLP_IN  608   // NODE_F + 3*EDGE_F + GLOB_F
#define K1PAD   640   // MLP_IN padded to multiple of 32

// ---------------- scratch (device globals: allocation-free) ----------------
__device__ float    g_sum[(size_t)N_NODES * EDGE_F];
__device__ unsigned g_maxu[(size_t)N_NODES * EDGE_F];
__device__ float    g_cnt[N_NODES];
// split-bf16 operands
__device__ alignas(16) __nv_bfloat16 g_Hh[(size_t)N_NODES * K1PAD];
__device__ alignas(16) __nv_bfloat16 g_Hl[(size_t)N_NODES * K1PAD];
__device__ alignas(16) __nv_bfloat16 g_midh[(size_t)N_NODES * HIDDEN];
__device__ alignas(16) __nv_bfloat16 g_midl[(size_t)N_NODES * HIDDEN];
__device__ alignas(16) __nv_bfloat16 g_Wt1h[(size_t)HIDDEN * K1PAD];
__device__ alignas(16) __nv_bfloat16 g_Wt1l[(size_t)HIDDEN * K1PAD];
__device__ alignas(16) __nv_bfloat16 g_Wt2h[(size_t)NODE_F * HIDDEN];
__device__ alignas(16) __nv_bfloat16 g_Wt2l[(size_t)NODE_F * HIDDEN];

// ======================= helpers ===========================================
__device__ __forceinline__ uint32_t smem_to_u32(const void* p) {
    uint32_t a;
    asm("{ .reg .u64 t; cvta.to.shared.u64 t, %1; cvt.u32.u64 %0, t; }"
        : "=r"(a) : "l"(p));
    return a;
}

__device__ __forceinline__ void cp16(uint32_t dst, const void* src, bool valid) {
    asm volatile("cp.async.cg.shared.global [%0], [%1], 16, %2;"
                 :: "r"(dst), "l"(src), "r"(valid ? 16 : 0));
}
#define CP_COMMIT() asm volatile("cp.async.commit_group;" ::: "memory")
#define CP_WAIT(n)  asm volatile("cp.async.wait_group %0;" :: "n"(n) : "memory")

__device__ __forceinline__ void ldsm4(uint32_t* r, uint32_t addr) {
    asm volatile("ldmatrix.sync.aligned.m8n8.x4.shared.b16 {%0,%1,%2,%3}, [%4];"
                 : "=r"(r[0]), "=r"(r[1]), "=r"(r[2]), "=r"(r[3]) : "r"(addr));
}

__device__ __forceinline__ void mma16816(float* d, const uint32_t* a,
                                         uint32_t b0, uint32_t b1) {
    asm volatile(
        "mma.sync.aligned.m16n8k16.row.col.f32.bf16.bf16.f32 "
        "{%0,%1,%2,%3}, {%4,%5,%6,%7}, {%8,%9}, {%0,%1,%2,%3};"
        : "+f"(d[0]), "+f"(d[1]), "+f"(d[2]), "+f"(d[3])
        : "r"(a[0]), "r"(a[1]), "r"(a[2]), "r"(a[3]), "r"(b0), "r"(b1));
}

__device__ __forceinline__ void split_f32(float v, __nv_bfloat16& h, __nv_bfloat16& l) {
    h = __float2bfloat16(v);
    l = __float2bfloat16(v - __bfloat162float(h));
}

// ========================= front-end kernels ===============================
__global__ void init_kernel() {
    const int total = N_NODES * EDGE_F;
    for (int i = blockIdx.x * blockDim.x + threadIdx.x; i < total;
         i += gridDim.x * blockDim.x) {
        g_sum[i]  = 0.0f;
        g_maxu[i] = 0xFF800000u;  // -inf bits
        if (i < N_NODES) g_cnt[i] = 0.0f;
    }
}

__device__ __forceinline__ void atomic_max_f32(unsigned* addr, float v) {
    if (v >= 0.0f) atomicMax((int*)addr, __float_as_int(v));
    else           atomicMin(addr, __float_as_uint(v));
}

__global__ void scatter_kernel(const float* __restrict__ edge_attr,
                               const int* __restrict__ col) {
    const int per_edge = EDGE_F / 4;  // 24 float4 groups
    int idx = blockIdx.x * blockDim.x + threadIdx.x;
    if (idx >= N_EDGES * per_edge) return;
    int e  = idx / per_edge;
    int f4 = idx - e * per_edge;
    int c  = col[e];

    float4 v = reinterpret_cast<const float4*>(edge_attr + (size_t)e * EDGE_F)[f4];
    size_t base = (size_t)c * EDGE_F + f4 * 4;

    atomicAdd(&g_sum[base + 0], v.x);
    atomicAdd(&g_sum[base + 1], v.y);
    atomicAdd(&g_sum[base + 2], v.z);
    atomicAdd(&g_sum[base + 3], v.w);

    atomic_max_f32(&g_maxu[base + 0], v.x);
    atomic_max_f32(&g_maxu[base + 1], v.y);
    atomic_max_f32(&g_maxu[base + 2], v.z);
    atomic_max_f32(&g_maxu[base + 3], v.w);

    if (f4 == 0) atomicAdd(&g_cnt[c], 1.0f);
}

// assemble concat row [x | sum | max | mean | u[batch] | zeros-to-640], split bf16
__global__ void assemble_kernel(const float* __restrict__ x,
                                const float* __restrict__ u,
                                const int* __restrict__ batch) {
    long long idx = (long long)blockIdx.x * blockDim.x + threadIdx.x;
    const long long total = (long long)N_NODES * K1PAD;
    if (idx >= total) return;
    int n = (int)(idx / K1PAD);
    int f = (int)(idx - (long long)n * K1PAD);

    float val;
    if (f < NODE_F) {
        val = x[(size_t)n * NODE_F + f];
    } else if (f < NODE_F + EDGE_F) {                    // sum
        val = g_sum[(size_t)n * EDGE_F + (f - NODE_F)];
    } else if (f < NODE_F + 2 * EDGE_F) {                // max (0 if empty)
        float c = g_cnt[n];
        val = (c > 0.0f)
            ? __uint_as_float(g_maxu[(size_t)n * EDGE_F + (f - NODE_F - EDGE_F)])
            : 0.0f;
    } else if (f < NODE_F + 3 * EDGE_F) {                // mean
        float c = g_cnt[n];
        val = g_sum[(size_t)n * EDGE_F + (f - NODE_F - 2 * EDGE_F)] / fmaxf(c, 1.0f);
    } else if (f < MLP_IN) {                             // u[batch[n]]
        val = u[(size_t)batch[n] * GLOB_F + (f - NODE_F - 3 * EDGE_F)];
    } else {
        val = 0.0f;                                      // pad
    }
    __nv_bfloat16 h, l;
    split_f32(val, h, l);
    g_Hh[idx] = h;
    g_Hl[idx] = l;
}

// W1 [MLP_IN,HIDDEN] -> Wt1 [HIDDEN][K1PAD] bf16 hi/lo (zero pad K)
__global__ void wt1_kernel(const float* __restrict__ W1) {
    int idx = blockIdx.x * blockDim.x + threadIdx.x;
    const int total = HIDDEN * K1PAD;
    if (idx >= total) return;
    int n = idx / K1PAD;
    int k = idx - n * K1PAD;
    float v = (k < MLP_IN) ? W1[(size_t)k * HIDDEN + n] : 0.0f;
    __nv_bfloat16 h, l;
    split_f32(v, h, l);
    g_Wt1h[idx] = h;
    g_Wt1l[idx] = l;
}

// W2 [HIDDEN,NODE_F] -> Wt2 [NODE_F][HIDDEN] bf16 hi/lo
__global__ void wt2_kernel(const float* __restrict__ W2) {
    int idx = blockIdx.x * blockDim.x + threadIdx.x;
    const int total = NODE_F * HIDDEN;
    if (idx >= total) return;
    int n = idx / HIDDEN;
    int k = idx - n * HIDDEN;
    float v = W2[(size_t)k * NODE_F + n];
    __nv_bfloat16 h, l;
    split_f32(v, h, l);
    g_Wt2h[idx] = h;
    g_Wt2l[idx] = l;
}

// ================= split-bf16 GEMM on mma.sync (HMMA) ======================
// C[128,128] tile per CTA, 8 warps in 2(M)x4(N), warp tile 64x32.
// A: [M][K_TOTAL] bf16 hi/lo row-major; B: [N_TOTAL][K_TOTAL] bf16 hi/lo
// (n-major, K contiguous -> acts as col-major k x n for mma).
// acc += Ah*Bh + Ah*Bl + Al*Bh  (3-product split, f32 accumulate)
// MODE 0: out = relu(acc + bias) -> bf16 hi/lo    MODE 1: out = acc+bias+resid -> f32
template<int K_TOTAL, int N_TOTAL, int MODE>
__global__ void __launch_bounds__(256, 1) hmma_gemm_kernel(
    const __nv_bfloat16* __restrict__ Ah, const __nv_bfloat16* __restrict__ Al,
    const __nv_bfloat16* __restrict__ Bh, const __nv_bfloat16* __restrict__ Bl,
    const float* __restrict__ bias, const float* __restrict__ resid,
    __nv_bfloat16* __restrict__ outh, __nv_bfloat16* __restrict__ outl,
    float* __restrict__ outf, int M)
{
    constexpr int KC = 32;           // K per chunk
    constexpr int S  = 3;            // pipeline stages
    constexpr int ROW_B  = 80;       // padded row bytes (32 bf16 = 64B -> 80B)
    constexpr int TILE_B = 128 * ROW_B;   // 10240
    constexpr int STAGE_B = 4 * TILE_B;   // Ah,Al,Bh,Bl
    constexpr int NCH = K_TOTAL / KC;

    extern __shared__ char smem[];
    const uint32_t smem_u = smem_to_u32(smem);

    const int tid = threadIdx.x;
    const int lid = tid & 31;
    const int wid = tid >> 5;
    const int warp_m = wid & 1;      // 0..1
    const int warp_n = wid >> 1;     // 0..3
    const int blockN = blockIdx.x * 128;
    const int blockM = blockIdx.y * 128;

    float acc[64];
    #pragma unroll
    for (int i = 0; i < 64; i++) acc[i] = 0.0f;

    // per-thread gmem->smem mapping: 512 16B-chunks per tile, 2 per thread
    const int ldrow0 = tid >> 2;     // 0..63
    const int ldseg  = tid & 3;      // 0..3 (16B segment within 64B row)

    auto load_chunk = [&](int c) {
        if (c >= NCH) return;
        const int kb = c * KC;
        const uint32_t sb = smem_u + (uint32_t)(c % S) * STAGE_B;
        #pragma unroll
        for (int i = 0; i < 2; i++) {
            const int row = ldrow0 + 64 * i;
            const uint32_t doff = (uint32_t)row * ROW_B + ldseg * 16;
            const int gr = blockM + row;
            const bool v = gr < M;
            const size_t goA = (size_t)(v ? gr : 0) * K_TOTAL + kb + ldseg * 8;
            cp16(sb + 0 * TILE_B + doff, Ah + goA, v);
            cp16(sb + 1 * TILE_B + doff, Al + goA, v);
            const size_t goB = (size_t)(blockN + row) * K_TOTAL + kb + ldseg * 8;
            cp16(sb + 2 * TILE_B + doff, Bh + goB, true);
            cp16(sb + 3 * TILE_B + doff, Bl + goB, true);
        }
    };

    // prologue: stage chunks 0..S-2
    #pragma unroll
    for (int c = 0; c < S - 1; c++) {
        load_chunk(c);
        CP_COMMIT();
    }

    const int lr = lid & 15;             // ldmatrix lane row
    const int lk = (lid >> 4) * 8;       // ldmatrix lane k offset

    for (int c = 0; c < NCH; c++) {
        load_chunk(c + S - 1);
        CP_COMMIT();
        CP_WAIT(S - 1);
        __syncthreads();

        const uint32_t sb = smem_u + (uint32_t)(c % S) * STAGE_B;
        const uint32_t aH = sb, aL = sb + TILE_B;
        const uint32_t bH = sb + 2 * TILE_B, bL = sb + 3 * TILE_B;

        #pragma unroll
        for (int kk = 0; kk < KC; kk += 16) {
            uint32_t bh[8], bl[8];
            #pragma unroll
            for (int bn = 0; bn < 2; bn++) {
                const uint32_t off =
                    (uint32_t)(warp_n * 32 + bn * 16 + lr) * ROW_B + (kk + lk) * 2;
                ldsm4(&bh[bn * 4], bH + off);
                ldsm4(&bl[bn * 4], bL + off);
            }
            #pragma unroll
            for (int am = 0; am < 4; am++) {
                uint32_t ah[4], al[4];
                const uint32_t off =
                    (uint32_t)(warp_m * 64 + am * 16 + lr) * ROW_B + (kk + lk) * 2;
                ldsm4(ah, aH + off);
                ldsm4(al, aL + off);
                #pragma unroll
                for (int an = 0; an < 4; an++) {
                    const int bn = an >> 1, sel = an & 1;
                    float* d = &acc[(am * 4 + an) * 4];
                    const uint32_t h0 = bh[bn * 4 + sel], h1 = bh[bn * 4 + sel + 2];
                    const uint32_t l0 = bl[bn * 4 + sel], l1 = bl[bn * 4 + sel + 2];
                    mma16816(d, ah, h0, h1);
                    mma16816(d, ah, l0, l1);
                    mma16816(d, al, h0, h1);
                }
            }
        }
        __syncthreads();
    }

    // ---------------- epilogue ----------------
    const int g = lid >> 2;          // 0..7
    const int t = lid & 3;           // 0..3
    #pragma unroll
    for (int am = 0; am < 4; am++) {
        #pragma unroll
        for (int an = 0; an < 4; an++) {
            const float* d = &acc[(am * 4 + an) * 4];
            const int col = blockN + warp_n * 32 + an * 8 + 2 * t;
            const float bia0 = bias[col], bia1 = bias[col + 1];
            #pragma unroll
            for (int half = 0; half < 2; half++) {
                const int row = blockM + warp_m * 64 + am * 16 + g + half * 8;
                if (row >= M) continue;
                float v0 = d[half * 2 + 0] + bia0;
                float v1 = d[half * 2 + 1] + bia1;
                const size_t o = (size_t)row * N_TOTAL + col;
                if (MODE == 0) {
                    v0 = fmaxf(v0, 0.0f);
                    v1 = fmaxf(v1, 0.0f);
                    __nv_bfloat16 h0, l0, h1, l1;
                    split_f32(v0, h0, l0);
                    split_f32(v1, h1, l1);
                    __nv_bfloat162 ph = __nv_bfloat162(h0, h1);
                    __nv_bfloat162 pl = __nv_bfloat162(l0, l1);
                    *reinterpret_cast<uint32_t*>(outh + o) = *reinterpret_cast<uint32_t*>(&ph);
                    *reinterpret_cast<uint32_t*>(outl + o) = *reinterpret_cast<uint32_t*>(&pl);
                } else {
                    float2 r;
                    r.x = v0 + resid[o];
                    r.y = v1 + resid[o + 1];
                    *reinterpret_cast<float2*>(outf + o) = r;
                }
            }
        }
    }
}

// ---------------- launch ----------------
extern "C" void kernel_launch(void* const* d_in, const int* in_sizes, int n_in,
                              void* d_out, int out_size) {
    const float* x         = (const float*)d_in[0];   // [50000, 256]
    const float* edge_attr = (const float*)d_in[1];   // [800000, 96]
    const float* u         = (const float*)d_in[2];   // [8, 64]
    const float* W1        = (const float*)d_in[3];   // [608, 1024]
    const float* b1        = (const float*)d_in[4];   // [1024]
    const float* W2        = (const float*)d_in[5];   // [1024, 256]
    const float* b2        = (const float*)d_in[6];   // [256]
    const int*   edge_index= (const int*)d_in[7];     // [2, 800000]
    const int*   batch     = (const int*)d_in[8];     // [50000]
    float* out = (float*)d_out;                       // [50000, 256]

    const int* col = edge_index + N_EDGES;

    __nv_bfloat16 *pHh, *pHl, *pMh, *pMl, *pW1h, *pW1l, *pW2h, *pW2l;
    cudaGetSymbolAddress((void**)&pHh,  g_Hh);
    cudaGetSymbolAddress((void**)&pHl,  g_Hl);
    cudaGetSymbolAddress((void**)&pMh,  g_midh);
    cudaGetSymbolAddress((void**)&pMl,  g_midl);
    cudaGetSymbolAddress((void**)&pW1h, g_Wt1h);
    cudaGetSymbolAddress((void**)&pW1l, g_Wt1l);
    cudaGetSymbolAddress((void**)&pW2h, g_Wt2h);
    cudaGetSymbolAddress((void**)&pW2l, g_Wt2l);

    const int SMEM_BYTES = 3 * 4 * 128 * 80;   // 122880
    cudaFuncSetAttribute(hmma_gemm_kernel<K1PAD, HIDDEN, 0>,
                         cudaFuncAttributeMaxDynamicSharedMemorySize, SMEM_BYTES);
    cudaFuncSetAttribute(hmma_gemm_kernel<HIDDEN, NODE_F, 1>,
                         cudaFuncAttributeMaxDynamicSharedMemorySize, SMEM_BYTES);

    // 1) init accumulators
    init_kernel<<<(N_NODES * EDGE_F + 255) / 256, 256>>>();
    // 2) scatter sum/max/count
    scatter_kernel<<<(N_EDGES * (EDGE_F / 4) + 255) / 256, 256>>>(edge_attr, col);
    // 3) weight prep (independent)
    wt1_kernel<<<(HIDDEN * K1PAD + 255) / 256, 256>>>(W1);
    wt2_kernel<<<(NODE_F * HIDDEN + 255) / 256, 256>>>(W2);
    // 4) assemble concat input (split bf16, padded to 640)
    {
        long long total = (long long)N_NODES * K1PAD;
        assemble_kernel<<<(int)((total + 255) / 256), 256>>>(x, u, batch);
    }
    // 5) GEMM1: mid = relu(H @ W1 + b1)  [50000,1024]
    {
        dim3 grid(HIDDEN / 128, (N_NODES + 127) / 128);
        hmma_gemm_kernel<K1PAD, HIDDEN, 0><<<grid, 256, SMEM_BYTES>>>(
            pHh, pHl, pW1h, pW1l, b1, nullptr, pMh, pMl, nullptr, N_NODES);
    }
    // 6) GEMM2: out = mid @ W2 + b2 + x  [50000,256]
    {
        dim3 grid(NODE_F / 128, (N_NODES + 127) / 128);
        hmma_gemm_kernel<HIDDEN, NODE_F, 1><<<grid, 256, SMEM_BYTES>>>(
            pMh, pMl, pW2h, pW2l, b2, x, nullptr, nullptr, out, N_NODES);
    }
}

// round 7
// speedup vs baseline: 1.9193x; 1.2673x over previous
#include <cuda_runtime.h>
#include <cuda_bf16.h>
#include <stdint.h>

#define N_NODES 50000
#define N_EDGES 800000
#define EDGE_F  96
#define NODE_F  256
#define GLOB_F  64
#define HIDDEN  1024
#define MLP_IN  608   // NODE_F + 3*EDGE_F + GLOB_F
#define K1PAD   640   // MLP_IN padded to multiple of 32

// ---------------- scratch (device globals: allocation-free) ----------------
__device__ int g_deg[N_NODES];
__device__ int g_off[N_NODES + 1];
__device__ int g_cur[N_NODES];
__device__ int g_bin[N_EDGES];
// split-bf16 operands
__device__ alignas(16) __nv_bfloat16 g_Hh[(size_t)N_NODES * K1PAD];
__device__ alignas(16) __nv_bfloat16 g_Hl[(size_t)N_NODES * K1PAD];
__device__ alignas(16) __nv_bfloat16 g_midh[(size_t)N_NODES * HIDDEN];
__device__ alignas(16) __nv_bfloat16 g_midl[(size_t)N_NODES * HIDDEN];
__device__ alignas(16) __nv_bfloat16 g_Wt1h[(size_t)HIDDEN * K1PAD];
__device__ alignas(16) __nv_bfloat16 g_Wt1l[(size_t)HIDDEN * K1PAD];
__device__ alignas(16) __nv_bfloat16 g_Wt2h[(size_t)NODE_F * HIDDEN];
__device__ alignas(16) __nv_bfloat16 g_Wt2l[(size_t)NODE_F * HIDDEN];

// ======================= helpers ===========================================
__device__ __forceinline__ uint32_t smem_to_u32(const void* p) {
    uint32_t a;
    asm("{ .reg .u64 t; cvta.to.shared.u64 t, %1; cvt.u32.u64 %0, t; }"
        : "=r"(a) : "l"(p));
    return a;
}

__device__ __forceinline__ void cp16(uint32_t dst, const void* src, bool valid) {
    asm volatile("cp.async.cg.shared.global [%0], [%1], 16, %2;"
                 :: "r"(dst), "l"(src), "r"(valid ? 16 : 0));
}
#define CP_COMMIT() asm volatile("cp.async.commit_group;" ::: "memory")
#define CP_WAIT(n)  asm volatile("cp.async.wait_group %0;" :: "n"(n) : "memory")

__device__ __forceinline__ void ldsm4(uint32_t* r, uint32_t addr) {
    asm volatile("ldmatrix.sync.aligned.m8n8.x4.shared.b16 {%0,%1,%2,%3}, [%4];"
                 : "=r"(r[0]), "=r"(r[1]), "=r"(r[2]), "=r"(r[3]) : "r"(addr));
}

__device__ __forceinline__ void mma16816(float* d, const uint32_t* a,
                                         uint32_t b0, uint32_t b1) {
    asm volatile(
        "mma.sync.aligned.m16n8k16.row.col.f32.bf16.bf16.f32 "
        "{%0,%1,%2,%3}, {%4,%5,%6,%7}, {%8,%9}, {%0,%1,%2,%3};"
        : "+f"(d[0]), "+f"(d[1]), "+f"(d[2]), "+f"(d[3])
        : "r"(a[0]), "r"(a[1]), "r"(a[2]), "r"(a[3]), "r"(b0), "r"(b1));
}

__device__ __forceinline__ void split_f32(float v, __nv_bfloat16& h, __nv_bfloat16& l) {
    h = __float2bfloat16(v);
    l = __float2bfloat16(v - __bfloat162float(h));
}

// ===================== CSR build + gather reduction ========================
__global__ void zero_deg_kernel() {
    int i = blockIdx.x * blockDim.x + threadIdx.x;
    if (i < N_NODES) g_deg[i] = 0;
}

__global__ void count_kernel(const int* __restrict__ col) {
    int e = blockIdx.x * blockDim.x + threadIdx.x;
    if (e < N_EDGES) atomicAdd(&g_deg[col[e]], 1);
}

// single-CTA chunked exclusive scan over g_deg -> g_off, g_cur
__global__ void scan_kernel() {
    __shared__ int warp_sums[32];
    __shared__ int carry_s;
    const int tid = threadIdx.x;
    const int lane = tid & 31, wid = tid >> 5;
    if (tid == 0) carry_s = 0;
    __syncthreads();
    for (int base = 0; base < N_NODES; base += 1024) {
        int i = base + tid;
        int v = (i < N_NODES) ? g_deg[i] : 0;
        int x = v;
        #pragma unroll
        for (int o = 1; o < 32; o <<= 1) {
            int y = __shfl_up_sync(0xFFFFFFFFu, x, o);
            if (lane >= o) x += y;
        }
        if (lane == 31) warp_sums[wid] = x;
        __syncthreads();
        if (wid == 0) {
            int w = warp_sums[lane];
            #pragma unroll
            for (int o = 1; o < 32; o <<= 1) {
                int y = __shfl_up_sync(0xFFFFFFFFu, w, o);
                if (lane >= o) w += y;
            }
            warp_sums[lane] = w;
        }
        __syncthreads();
        int excl = x - v + (wid > 0 ? warp_sums[wid - 1] : 0) + carry_s;
        if (i < N_NODES) {
            g_off[i] = excl;
            g_cur[i] = excl;
        }
        __syncthreads();
        if (tid == 0) carry_s += warp_sums[31];
        __syncthreads();
    }
    if (tid == 0) g_off[N_NODES] = N_EDGES;
}

__global__ void fill_kernel(const int* __restrict__ col) {
    int e = blockIdx.x * blockDim.x + threadIdx.x;
    if (e < N_EDGES) {
        int pos = atomicAdd(&g_cur[col[e]], 1);
        g_bin[pos] = e;
    }
}

// warp-per-node gather: sum/max/mean over this node's edges, write split-bf16
// into H columns [256, 544): [sum(96) | max(96) | mean(96)]
__global__ void gather_kernel(const float* __restrict__ edge_attr) {
    const int warp_g = (blockIdx.x * blockDim.x + threadIdx.x) >> 5;
    if (warp_g >= N_NODES) return;
    const int lane = threadIdx.x & 31;
    const int beg = g_off[warp_g];
    const int end = g_off[warp_g + 1];

    float s0 = 0.f, s1 = 0.f, s2 = 0.f;
    float m0 = -__int_as_float(0x7F800000), m1 = m0, m2 = m0;  // -inf

    for (int i = beg; i < end; i++) {
        const int e = g_bin[i];
        const float* row = edge_attr + (size_t)e * EDGE_F;
        float v0 = row[lane];
        float v1 = row[lane + 32];
        float v2 = row[lane + 64];
        s0 += v0; s1 += v1; s2 += v2;
        m0 = fmaxf(m0, v0); m1 = fmaxf(m1, v1); m2 = fmaxf(m2, v2);
    }
    const int cnt = end - beg;
    if (cnt == 0) { m0 = 0.f; m1 = 0.f; m2 = 0.f; }
    const float inv = 1.0f / (float)max(cnt, 1);

    const size_t rb = (size_t)warp_g * K1PAD;
    __nv_bfloat16 h, l;
    // sum cols 256..352
    split_f32(s0, h, l); g_Hh[rb + 256 + lane] = h; g_Hl[rb + 256 + lane] = l;
    split_f32(s1, h, l); g_Hh[rb + 288 + lane] = h; g_Hl[rb + 288 + lane] = l;
    split_f32(s2, h, l); g_Hh[rb + 320 + lane] = h; g_Hl[rb + 320 + lane] = l;
    // max cols 352..448
    split_f32(m0, h, l); g_Hh[rb + 352 + lane] = h; g_Hl[rb + 352 + lane] = l;
    split_f32(m1, h, l); g_Hh[rb + 384 + lane] = h; g_Hl[rb + 384 + lane] = l;
    split_f32(m2, h, l); g_Hh[rb + 416 + lane] = h; g_Hl[rb + 416 + lane] = l;
    // mean cols 448..544
    split_f32(s0 * inv, h, l); g_Hh[rb + 448 + lane] = h; g_Hl[rb + 448 + lane] = l;
    split_f32(s1 * inv, h, l); g_Hh[rb + 480 + lane] = h; g_Hl[rb + 480 + lane] = l;
    split_f32(s2 * inv, h, l); g_Hh[rb + 512 + lane] = h; g_Hl[rb + 512 + lane] = l;
}

// fill H columns [0,256) = x, [544,608) = u[batch], [608,640) = 0
__global__ void rest_kernel(const float* __restrict__ x,
                            const float* __restrict__ u,
                            const int* __restrict__ batch) {
    const int COLS = NODE_F + GLOB_F + (K1PAD - MLP_IN);  // 352
    long long idx = (long long)blockIdx.x * blockDim.x + threadIdx.x;
    const long long total = (long long)N_NODES * COLS;
    if (idx >= total) return;
    int n = (int)(idx / COLS);
    int c = (int)(idx - (long long)n * COLS);

    float val;
    int f;  // actual H column
    if (c < NODE_F) {
        f = c;
        val = x[(size_t)n * NODE_F + c];
    } else if (c < NODE_F + GLOB_F) {
        f = 544 + (c - NODE_F);
        val = u[(size_t)batch[n] * GLOB_F + (c - NODE_F)];
    } else {
        f = MLP_IN + (c - NODE_F - GLOB_F);
        val = 0.0f;
    }
    __nv_bfloat16 h, l;
    split_f32(val, h, l);
    g_Hh[(size_t)n * K1PAD + f] = h;
    g_Hl[(size_t)n * K1PAD + f] = l;
}

// W1 [MLP_IN,HIDDEN] -> Wt1 [HIDDEN][K1PAD] bf16 hi/lo (zero pad K)
__global__ void wt1_kernel(const float* __restrict__ W1) {
    int idx = blockIdx.x * blockDim.x + threadIdx.x;
    const int total = HIDDEN * K1PAD;
    if (idx >= total) return;
    int n = idx / K1PAD;
    int k = idx - n * K1PAD;
    float v = (k < MLP_IN) ? W1[(size_t)k * HIDDEN + n] : 0.0f;
    __nv_bfloat16 h, l;
    split_f32(v, h, l);
    g_Wt1h[idx] = h;
    g_Wt1l[idx] = l;
}

// W2 [HIDDEN,NODE_F] -> Wt2 [NODE_F][HIDDEN] bf16 hi/lo
__global__ void wt2_kernel(const float* __restrict__ W2) {
    int idx = blockIdx.x * blockDim.x + threadIdx.x;
    const int total = NODE_F * HIDDEN;
    if (idx >= total) return;
    int n = idx / HIDDEN;
    int k = idx - n * HIDDEN;
    float v = W2[(size_t)k * NODE_F + n];
    __nv_bfloat16 h, l;
    split_f32(v, h, l);
    g_Wt2h[idx] = h;
    g_Wt2l[idx] = l;
}

// ================= split-bf16 GEMM on mma.sync (HMMA) ======================
// C[128,128] tile per CTA, 8 warps in 2(M)x4(N), warp tile 64x32.
// acc += Ah*Bh + Ah*Bl + Al*Bh  (3-product split, f32 accumulate)
// MODE 0: out = relu(acc + bias) -> bf16 hi/lo    MODE 1: out = acc+bias+resid -> f32
template<int K_TOTAL, int N_TOTAL, int MODE>
__global__ void __launch_bounds__(256, 1) hmma_gemm_kernel(
    const __nv_bfloat16* __restrict__ Ah, const __nv_bfloat16* __restrict__ Al,
    const __nv_bfloat16* __restrict__ Bh, const __nv_bfloat16* __restrict__ Bl,
    const float* __restrict__ bias, const float* __restrict__ resid,
    __nv_bfloat16* __restrict__ outh, __nv_bfloat16* __restrict__ outl,
    float* __restrict__ outf, int M)
{
    constexpr int KC = 32;
    constexpr int S  = 3;
    constexpr int ROW_B  = 80;
    constexpr int TILE_B = 128 * ROW_B;
    constexpr int STAGE_B = 4 * TILE_B;
    constexpr int NCH = K_TOTAL / KC;

    extern __shared__ char smem[];
    const uint32_t smem_u = smem_to_u32(smem);

    const int tid = threadIdx.x;
    const int lid = tid & 31;
    const int wid = tid >> 5;
    const int warp_m = wid & 1;
    const int warp_n = wid >> 1;
    const int blockN = blockIdx.x * 128;
    const int blockM = blockIdx.y * 128;

    float acc[64];
    #pragma unroll
    for (int i = 0; i < 64; i++) acc[i] = 0.0f;

    const int ldrow0 = tid >> 2;
    const int ldseg  = tid & 3;

    auto load_chunk = [&](int c) {
        if (c >= NCH) return;
        const int kb = c * KC;
        const uint32_t sb = smem_u + (uint32_t)(c % S) * STAGE_B;
        #pragma unroll
        for (int i = 0; i < 2; i++) {
            const int row = ldrow0 + 64 * i;
            const uint32_t doff = (uint32_t)row * ROW_B + ldseg * 16;
            const int gr = blockM + row;
            const bool v = gr < M;
            const size_t goA = (size_t)(v ? gr : 0) * K_TOTAL + kb + ldseg * 8;
            cp16(sb + 0 * TILE_B + doff, Ah + goA, v);
            cp16(sb + 1 * TILE_B + doff, Al + goA, v);
            const size_t goB = (size_t)(blockN + row) * K_TOTAL + kb + ldseg * 8;
            cp16(sb + 2 * TILE_B + doff, Bh + goB, true);
            cp16(sb + 3 * TILE_B + doff, Bl + goB, true);
        }
    };

    #pragma unroll
    for (int c = 0; c < S - 1; c++) {
        load_chunk(c);
        CP_COMMIT();
    }

    const int lr = lid & 15;
    const int lk = (lid >> 4) * 8;

    for (int c = 0; c < NCH; c++) {
        load_chunk(c + S - 1);
        CP_COMMIT();
        CP_WAIT(S - 1);
        __syncthreads();

        const uint32_t sb = smem_u + (uint32_t)(c % S) * STAGE_B;
        const uint32_t aH = sb, aL = sb + TILE_B;
        const uint32_t bH = sb + 2 * TILE_B, bL = sb + 3 * TILE_B;

        #pragma unroll
        for (int kk = 0; kk < KC; kk += 16) {
            uint32_t bh[8], bl[8];
            #pragma unroll
            for (int bn = 0; bn < 2; bn++) {
                const uint32_t off =
                    (uint32_t)(warp_n * 32 + bn * 16 + lr) * ROW_B + (kk + lk) * 2;
                ldsm4(&bh[bn * 4], bH + off);
                ldsm4(&bl[bn * 4], bL + off);
            }
            #pragma unroll
            for (int am = 0; am < 4; am++) {
                uint32_t ah[4], al[4];
                const uint32_t off =
                    (uint32_t)(warp_m * 64 + am * 16 + lr) * ROW_B + (kk + lk) * 2;
                ldsm4(ah, aH + off);
                ldsm4(al, aL + off);
                #pragma unroll
                for (int an = 0; an < 4; an++) {
                    const int bn = an >> 1, sel = an & 1;
                    float* d = &acc[(am * 4 + an) * 4];
                    const uint32_t h0 = bh[bn * 4 + sel], h1 = bh[bn * 4 + sel + 2];
                    const uint32_t l0 = bl[bn * 4 + sel], l1 = bl[bn * 4 + sel + 2];
                    mma16816(d, ah, h0, h1);
                    mma16816(d, ah, l0, l1);
                    mma16816(d, al, h0, h1);
                }
            }
        }
        __syncthreads();
    }

    const int g = lid >> 2;
    const int t = lid & 3;
    #pragma unroll
    for (int am = 0; am < 4; am++) {
        #pragma unroll
        for (int an = 0; an < 4; an++) {
            const float* d = &acc[(am * 4 + an) * 4];
            const int col = blockN + warp_n * 32 + an * 8 + 2 * t;
            const float bia0 = bias[col], bia1 = bias[col + 1];
            #pragma unroll
            for (int half = 0; half < 2; half++) {
                const int row = blockM + warp_m * 64 + am * 16 + g + half * 8;
                if (row >= M) continue;
                float v0 = d[half * 2 + 0] + bia0;
                float v1 = d[half * 2 + 1] + bia1;
                const size_t o = (size_t)row * N_TOTAL + col;
                if (MODE == 0) {
                    v0 = fmaxf(v0, 0.0f);
                    v1 = fmaxf(v1, 0.0f);
                    __nv_bfloat16 h0, l0, h1, l1;
                    split_f32(v0, h0, l0);
                    split_f32(v1, h1, l1);
                    __nv_bfloat162 ph = __nv_bfloat162(h0, h1);
                    __nv_bfloat162 pl = __nv_bfloat162(l0, l1);
                    *reinterpret_cast<uint32_t*>(outh + o) = *reinterpret_cast<uint32_t*>(&ph);
                    *reinterpret_cast<uint32_t*>(outl + o) = *reinterpret_cast<uint32_t*>(&pl);
                } else {
                    float2 r;
                    r.x = v0 + resid[o];
                    r.y = v1 + resid[o + 1];
                    *reinterpret_cast<float2*>(outf + o) = r;
                }
            }
        }
    }
}

// ---------------- launch ----------------
extern "C" void kernel_launch(void* const* d_in, const int* in_sizes, int n_in,
                              void* d_out, int out_size) {
    const float* x         = (const float*)d_in[0];   // [50000, 256]
    const float* edge_attr = (const float*)d_in[1];   // [800000, 96]
    const float* u         = (const float*)d_in[2];   // [8, 64]
    const float* W1        = (const float*)d_in[3];   // [608, 1024]
    const float* b1        = (const float*)d_in[4];   // [1024]
    const float* W2        = (const float*)d_in[5];   // [1024, 256]
    const float* b2        = (const float*)d_in[6];   // [256]
    const int*   edge_index= (const int*)d_in[7];     // [2, 800000]
    const int*   batch     = (const int*)d_in[8];     // [50000]
    float* out = (float*)d_out;                       // [50000, 256]

    const int* col = edge_index + N_EDGES;

    __nv_bfloat16 *pHh, *pHl, *pMh, *pMl, *pW1h, *pW1l, *pW2h, *pW2l;
    cudaGetSymbolAddress((void**)&pHh,  g_Hh);
    cudaGetSymbolAddress((void**)&pHl,  g_Hl);
    cudaGetSymbolAddress((void**)&pMh,  g_midh);
    cudaGetSymbolAddress((void**)&pMl,  g_midl);
    cudaGetSymbolAddress((void**)&pW1h, g_Wt1h);
    cudaGetSymbolAddress((void**)&pW1l, g_Wt1l);
    cudaGetSymbolAddress((void**)&pW2h, g_Wt2h);
    cudaGetSymbolAddress((void**)&pW2l, g_Wt2l);

    const int SMEM_BYTES = 3 * 4 * 128 * 80;   // 122880
    cudaFuncSetAttribute(hmma_gemm_kernel<K1PAD, HIDDEN, 0>,
                         cudaFuncAttributeMaxDynamicSharedMemorySize, SMEM_BYTES);
    cudaFuncSetAttribute(hmma_gemm_kernel<HIDDEN, NODE_F, 1>,
                         cudaFuncAttributeMaxDynamicSharedMemorySize, SMEM_BYTES);

    // --- CSR build + gather reduction (replaces atomic scatter) ---
    zero_deg_kernel<<<(N_NODES + 255) / 256, 256>>>();
    count_kernel<<<(N_EDGES + 255) / 256, 256>>>(col);
    scan_kernel<<<1, 1024>>>();
    fill_kernel<<<(N_EDGES + 255) / 256, 256>>>(col);
    gather_kernel<<<(N_NODES * 32 + 255) / 256, 256>>>(edge_attr);

    // --- independent prep ---
    wt1_kernel<<<(HIDDEN * K1PAD + 255) / 256, 256>>>(W1);
    wt2_kernel<<<(NODE_F * HIDDEN + 255) / 256, 256>>>(W2);
    {
        const int COLS = NODE_F + GLOB_F + (K1PAD - MLP_IN);
        long long total = (long long)N_NODES * COLS;
        rest_kernel<<<(int)((total + 255) / 256), 256>>>(x, u, batch);
    }

    // GEMM1: mid = relu(H @ W1 + b1)  [50000,1024]
    {
        dim3 grid(HIDDEN / 128, (N_NODES + 127) / 128);
        hmma_gemm_kernel<K1PAD, HIDDEN, 0><<<grid, 256, SMEM_BYTES>>>(
            pHh, pHl, pW1h, pW1l, b1, nullptr, pMh, pMl, nullptr, N_NODES);
    }
    // GEMM2: out = mid @ W2 + b2 + x  [50000,256]
    {
        dim3 grid(NODE_F / 128, (N_NODES + 127) / 128);
        hmma_gemm_kernel<HIDDEN, NODE_F, 1><<<grid, 256, SMEM_BYTES>>>(
            pMh, pMl, pW2h, pW2l, b2, x, nullptr, nullptr, out, N_NODES);
    }
}

// round 8
// speedup vs baseline: 2.4856x; 1.2951x over previous
#include <cuda_runtime.h>
#include <cuda_bf16.h>
#include <stdint.h>

#define N_NODES 50000
#define N_EDGES 800000
#define EDGE_F  96
#define NODE_F  256
#define GLOB_F  64
#define HIDDEN  1024
#define MLP_IN  608   // NODE_F + 3*EDGE_F + GLOB_F
#define K1PAD   640   // MLP_IN padded to multiple of 32

// ---------------- scratch (device globals: allocation-free) ----------------
__device__ int g_deg[N_NODES];
__device__ int g_off[N_NODES + 1];
__device__ int g_cur[N_NODES];
__device__ int g_bin[N_EDGES];
// split-bf16 operands
__device__ alignas(16) __nv_bfloat16 g_Hh[(size_t)N_NODES * K1PAD];
__device__ alignas(16) __nv_bfloat16 g_Hl[(size_t)N_NODES * K1PAD];
__device__ alignas(16) __nv_bfloat16 g_midh[(size_t)N_NODES * HIDDEN];
__device__ alignas(16) __nv_bfloat16 g_midl[(size_t)N_NODES * HIDDEN];
__device__ alignas(16) __nv_bfloat16 g_Wt1h[(size_t)HIDDEN * K1PAD];
__device__ alignas(16) __nv_bfloat16 g_Wt1l[(size_t)HIDDEN * K1PAD];
__device__ alignas(16) __nv_bfloat16 g_Wt2h[(size_t)NODE_F * HIDDEN];
__device__ alignas(16) __nv_bfloat16 g_Wt2l[(size_t)NODE_F * HIDDEN];

// ======================= helpers ===========================================
__device__ __forceinline__ uint32_t smem_to_u32(const void* p) {
    uint32_t a;
    asm("{ .reg .u64 t; cvta.to.shared.u64 t, %1; cvt.u32.u64 %0, t; }"
        : "=r"(a) : "l"(p));
    return a;
}

__device__ __forceinline__ void cp16(uint32_t dst, const void* src, bool valid) {
    asm volatile("cp.async.cg.shared.global [%0], [%1], 16, %2;"
                 :: "r"(dst), "l"(src), "r"(valid ? 16 : 0));
}
#define CP_COMMIT() asm volatile("cp.async.commit_group;" ::: "memory")
#define CP_WAIT(n)  asm volatile("cp.async.wait_group %0;" :: "n"(n) : "memory")

__device__ __forceinline__ void ldsm4(uint32_t* r, uint32_t addr) {
    asm volatile("ldmatrix.sync.aligned.m8n8.x4.shared.b16 {%0,%1,%2,%3}, [%4];"
                 : "=r"(r[0]), "=r"(r[1]), "=r"(r[2]), "=r"(r[3]) : "r"(addr));
}

__device__ __forceinline__ void mma16816(float* d, const uint32_t* a,
                                         uint32_t b0, uint32_t b1) {
    asm volatile(
        "mma.sync.aligned.m16n8k16.row.col.f32.bf16.bf16.f32 "
        "{%0,%1,%2,%3}, {%4,%5,%6,%7}, {%8,%9}, {%0,%1,%2,%3};"
        : "+f"(d[0]), "+f"(d[1]), "+f"(d[2]), "+f"(d[3])
        : "r"(a[0]), "r"(a[1]), "r"(a[2]), "r"(a[3]), "r"(b0), "r"(b1));
}

__device__ __forceinline__ void split_f32(float v, __nv_bfloat16& h, __nv_bfloat16& l) {
    h = __float2bfloat16(v);
    l = __float2bfloat16(v - __bfloat162float(h));
}

// 64B-row smem tile with XOR swizzle: row r, 16B-chunk c -> conflict-free
// for 8-lane ldmatrix phases: slot (4r + c^((r>>1)&3)) mod 8 is a bijection.
__device__ __forceinline__ uint32_t sw_off(int row, int chunk) {
    return (uint32_t)row * 64u + (uint32_t)((chunk ^ ((row >> 1) & 3)) << 4);
}

// ===================== CSR build + gather reduction ========================
__global__ void zero_deg_kernel() {
    int i = blockIdx.x * blockDim.x + threadIdx.x;
    if (i < N_NODES) g_deg[i] = 0;
}

__global__ void count_kernel(const int* __restrict__ col) {
    int e = blockIdx.x * blockDim.x + threadIdx.x;
    if (e < N_EDGES) atomicAdd(&g_deg[col[e]], 1);
}

// single-CTA chunked exclusive scan over g_deg -> g_off, g_cur
__global__ void scan_kernel() {
    __shared__ int warp_sums[32];
    __shared__ int carry_s;
    const int tid = threadIdx.x;
    const int lane = tid & 31, wid = tid >> 5;
    if (tid == 0) carry_s = 0;
    __syncthreads();
    for (int base = 0; base < N_NODES; base += 1024) {
        int i = base + tid;
        int v = (i < N_NODES) ? g_deg[i] : 0;
        int x = v;
        #pragma unroll
        for (int o = 1; o < 32; o <<= 1) {
            int y = __shfl_up_sync(0xFFFFFFFFu, x, o);
            if (lane >= o) x += y;
        }
        if (lane == 31) warp_sums[wid] = x;
        __syncthreads();
        if (wid == 0) {
            int w = warp_sums[lane];
            #pragma unroll
            for (int o = 1; o < 32; o <<= 1) {
                int y = __shfl_up_sync(0xFFFFFFFFu, w, o);
                if (lane >= o) w += y;
            }
            warp_sums[lane] = w;
        }
        __syncthreads();
        int excl = x - v + (wid > 0 ? warp_sums[wid - 1] : 0) + carry_s;
        if (i < N_NODES) {
            g_off[i] = excl;
            g_cur[i] = excl;
        }
        __syncthreads();
        if (tid == 0) carry_s += warp_sums[31];
        __syncthreads();
    }
    if (tid == 0) g_off[N_NODES] = N_EDGES;
}

__global__ void fill_kernel(const int* __restrict__ col) {
    int e = blockIdx.x * blockDim.x + threadIdx.x;
    if (e < N_EDGES) {
        int pos = atomicAdd(&g_cur[col[e]], 1);
        g_bin[pos] = e;
    }
}

// warp-per-node gather: sum/max/mean over this node's edges, write split-bf16
// into H columns [256, 544): [sum(96) | max(96) | mean(96)]
__global__ void gather_kernel(const float* __restrict__ edge_attr) {
    const int warp_g = (blockIdx.x * blockDim.x + threadIdx.x) >> 5;
    if (warp_g >= N_NODES) return;
    const int lane = threadIdx.x & 31;
    const int beg = g_off[warp_g];
    const int end = g_off[warp_g + 1];

    float s0 = 0.f, s1 = 0.f, s2 = 0.f;
    float m0 = -__int_as_float(0x7F800000), m1 = m0, m2 = m0;  // -inf

    for (int i = beg; i < end; i++) {
        const int e = g_bin[i];
        const float* row = edge_attr + (size_t)e * EDGE_F;
        float v0 = row[lane];
        float v1 = row[lane + 32];
        float v2 = row[lane + 64];
        s0 += v0; s1 += v1; s2 += v2;
        m0 = fmaxf(m0, v0); m1 = fmaxf(m1, v1); m2 = fmaxf(m2, v2);
    }
    const int cnt = end - beg;
    if (cnt == 0) { m0 = 0.f; m1 = 0.f; m2 = 0.f; }
    const float inv = 1.0f / (float)max(cnt, 1);

    const size_t rb = (size_t)warp_g * K1PAD;
    __nv_bfloat16 h, l;
    split_f32(s0, h, l); g_Hh[rb + 256 + lane] = h; g_Hl[rb + 256 + lane] = l;
    split_f32(s1, h, l); g_Hh[rb + 288 + lane] = h; g_Hl[rb + 288 + lane] = l;
    split_f32(s2, h, l); g_Hh[rb + 320 + lane] = h; g_Hl[rb + 320 + lane] = l;
    split_f32(m0, h, l); g_Hh[rb + 352 + lane] = h; g_Hl[rb + 352 + lane] = l;
    split_f32(m1, h, l); g_Hh[rb + 384 + lane] = h; g_Hl[rb + 384 + lane] = l;
    split_f32(m2, h, l); g_Hh[rb + 416 + lane] = h; g_Hl[rb + 416 + lane] = l;
    split_f32(s0 * inv, h, l); g_Hh[rb + 448 + lane] = h; g_Hl[rb + 448 + lane] = l;
    split_f32(s1 * inv, h, l); g_Hh[rb + 480 + lane] = h; g_Hl[rb + 480 + lane] = l;
    split_f32(s2 * inv, h, l); g_Hh[rb + 512 + lane] = h; g_Hl[rb + 512 + lane] = l;
}

// fill H columns [0,256) = x, [544,608) = u[batch], [608,640) = 0
__global__ void rest_kernel(const float* __restrict__ x,
                            const float* __restrict__ u,
                            const int* __restrict__ batch) {
    const int COLS = NODE_F + GLOB_F + (K1PAD - MLP_IN);  // 352
    long long idx = (long long)blockIdx.x * blockDim.x + threadIdx.x;
    const long long total = (long long)N_NODES * COLS;
    if (idx >= total) return;
    int n = (int)(idx / COLS);
    int c = (int)(idx - (long long)n * COLS);

    float val;
    int f;  // actual H column
    if (c < NODE_F) {
        f = c;
        val = x[(size_t)n * NODE_F + c];
    } else if (c < NODE_F + GLOB_F) {
        f = 544 + (c - NODE_F);
        val = u[(size_t)batch[n] * GLOB_F + (c - NODE_F)];
    } else {
        f = MLP_IN + (c - NODE_F - GLOB_F);
        val = 0.0f;
    }
    __nv_bfloat16 h, l;
    split_f32(val, h, l);
    g_Hh[(size_t)n * K1PAD + f] = h;
    g_Hl[(size_t)n * K1PAD + f] = l;
}

// W1 [MLP_IN,HIDDEN] -> Wt1 [HIDDEN][K1PAD] bf16 hi/lo (zero pad K)
__global__ void wt1_kernel(const float* __restrict__ W1) {
    int idx = blockIdx.x * blockDim.x + threadIdx.x;
    const int total = HIDDEN * K1PAD;
    if (idx >= total) return;
    int n = idx / K1PAD;
    int k = idx - n * K1PAD;
    float v = (k < MLP_IN) ? W1[(size_t)k * HIDDEN + n] : 0.0f;
    __nv_bfloat16 h, l;
    split_f32(v, h, l);
    g_Wt1h[idx] = h;
    g_Wt1l[idx] = l;
}

// W2 [HIDDEN,NODE_F] -> Wt2 [NODE_F][HIDDEN] bf16 hi/lo
__global__ void wt2_kernel(const float* __restrict__ W2) {
    int idx = blockIdx.x * blockDim.x + threadIdx.x;
    const int total = NODE_F * HIDDEN;
    if (idx >= total) return;
    int n = idx / HIDDEN;
    int k = idx - n * HIDDEN;
    float v = W2[(size_t)k * NODE_F + n];
    __nv_bfloat16 h, l;
    split_f32(v, h, l);
    g_Wt2h[idx] = h;
    g_Wt2l[idx] = l;
}

// ================= split-bf16 GEMM on mma.sync (HMMA) ======================
// C[128,128] tile per CTA, 8 warps in 2(M)x4(N), warp tile 64x32.
// 64B smem rows + XOR swizzle -> 32KB/stage, 3 stages = 96KB -> 2 CTAs/SM.
// acc += Ah*Bh + Ah*Bl + Al*Bh  (3-product split, f32 accumulate)
// MODE 0: out = relu(acc + bias) -> bf16 hi/lo    MODE 1: out = acc+bias+resid -> f32
template<int K_TOTAL, int N_TOTAL, int MODE>
__global__ void __launch_bounds__(256, 2) hmma_gemm_kernel(
    const __nv_bfloat16* __restrict__ Ah, const __nv_bfloat16* __restrict__ Al,
    const __nv_bfloat16* __restrict__ Bh, const __nv_bfloat16* __restrict__ Bl,
    const float* __restrict__ bias, const float* __restrict__ resid,
    __nv_bfloat16* __restrict__ outh, __nv_bfloat16* __restrict__ outl,
    float* __restrict__ outf, int M)
{
    constexpr int KC = 32;
    constexpr int S  = 3;
    constexpr int TILE_B = 128 * 64;      // 8192
    constexpr int STAGE_B = 4 * TILE_B;   // 32768
    constexpr int NCH = K_TOTAL / KC;

    extern __shared__ char smem[];
    const uint32_t smem_u = smem_to_u32(smem);

    const int tid = threadIdx.x;
    const int lid = tid & 31;
    const int wid = tid >> 5;
    const int warp_m = wid & 1;
    const int warp_n = wid >> 1;
    const int blockN = blockIdx.x * 128;
    const int blockM = blockIdx.y * 128;

    float acc[64];
    #pragma unroll
    for (int i = 0; i < 64; i++) acc[i] = 0.0f;

    const int ldrow0 = tid >> 2;     // 0..63
    const int ldseg  = tid & 3;      // 16B chunk within 64B row

    auto load_chunk = [&](int c) {
        if (c >= NCH) return;
        const int kb = c * KC;
        const uint32_t sb = smem_u + (uint32_t)(c % S) * STAGE_B;
        #pragma unroll
        for (int i = 0; i < 2; i++) {
            const int row = ldrow0 + 64 * i;
            const uint32_t doff = sw_off(row, ldseg);
            const int gr = blockM + row;
            const bool v = gr < M;
            const size_t goA = (size_t)(v ? gr : 0) * K_TOTAL + kb + ldseg * 8;
            cp16(sb + 0 * TILE_B + doff, Ah + goA, v);
            cp16(sb + 1 * TILE_B + doff, Al + goA, v);
            const size_t goB = (size_t)(blockN + row) * K_TOTAL + kb + ldseg * 8;
            cp16(sb + 2 * TILE_B + doff, Bh + goB, true);
            cp16(sb + 3 * TILE_B + doff, Bl + goB, true);
        }
    };

    #pragma unroll
    for (int c = 0; c < S - 1; c++) {
        load_chunk(c);
        CP_COMMIT();
    }

    const int lr = lid & 15;             // ldmatrix lane row
    const int lk = (lid >> 4) * 8;       // ldmatrix lane k offset (bf16 elems)

    for (int c = 0; c < NCH; c++) {
        load_chunk(c + S - 1);
        CP_COMMIT();
        CP_WAIT(S - 1);
        __syncthreads();

        const uint32_t sb = smem_u + (uint32_t)(c % S) * STAGE_B;
        const uint32_t aH = sb, aL = sb + TILE_B;
        const uint32_t bH = sb + 2 * TILE_B, bL = sb + 3 * TILE_B;

        #pragma unroll
        for (int kk = 0; kk < KC; kk += 16) {
            const int kchunk = (kk + lk) >> 3;   // 16B chunk index 0..3
            uint32_t bh[8], bl[8];
            #pragma unroll
            for (int bn = 0; bn < 2; bn++) {
                const uint32_t off = sw_off(warp_n * 32 + bn * 16 + lr, kchunk);
                ldsm4(&bh[bn * 4], bH + off);
                ldsm4(&bl[bn * 4], bL + off);
            }
            #pragma unroll
            for (int am = 0; am < 4; am++) {
                uint32_t ah[4], al[4];
                const uint32_t off = sw_off(warp_m * 64 + am * 16 + lr, kchunk);
                ldsm4(ah, aH + off);
                ldsm4(al, aL + off);
                #pragma unroll
                for (int an = 0; an < 4; an++) {
                    const int bn = an >> 1, sel = an & 1;
                    float* d = &acc[(am * 4 + an) * 4];
                    const uint32_t h0 = bh[bn * 4 + sel], h1 = bh[bn * 4 + sel + 2];
                    const uint32_t l0 = bl[bn * 4 + sel], l1 = bl[bn * 4 + sel + 2];
                    mma16816(d, ah, h0, h1);
                    mma16816(d, ah, l0, l1);
                    mma16816(d, al, h0, h1);
                }
            }
        }
        __syncthreads();
    }

    const int g = lid >> 2;
    const int t = lid & 3;
    #pragma unroll
    for (int am = 0; am < 4; am++) {
        #pragma unroll
        for (int an = 0; an < 4; an++) {
            const float* d = &acc[(am * 4 + an) * 4];
            const int col = blockN + warp_n * 32 + an * 8 + 2 * t;
            const float bia0 = bias[col], bia1 = bias[col + 1];
            #pragma unroll
            for (int half = 0; half < 2; half++) {
                const int row = blockM + warp_m * 64 + am * 16 + g + half * 8;
                if (row >= M) continue;
                float v0 = d[half * 2 + 0] + bia0;
                float v1 = d[half * 2 + 1] + bia1;
                const size_t o = (size_t)row * N_TOTAL + col;
                if (MODE == 0) {
                    v0 = fmaxf(v0, 0.0f);
                    v1 = fmaxf(v1, 0.0f);
                    __nv_bfloat16 h0, l0, h1, l1;
                    split_f32(v0, h0, l0);
                    split_f32(v1, h1, l1);
                    __nv_bfloat162 ph = __nv_bfloat162(h0, h1);
                    __nv_bfloat162 pl = __nv_bfloat162(l0, l1);
                    *reinterpret_cast<uint32_t*>(outh + o) = *reinterpret_cast<uint32_t*>(&ph);
                    *reinterpret_cast<uint32_t*>(outl + o) = *reinterpret_cast<uint32_t*>(&pl);
                } else {
                    float2 r;
                    r.x = v0 + resid[o];
                    r.y = v1 + resid[o + 1];
                    *reinterpret_cast<float2*>(outf + o) = r;
                }
            }
        }
    }
}

// ---------------- launch ----------------
extern "C" void kernel_launch(void* const* d_in, const int* in_sizes, int n_in,
                              void* d_out, int out_size) {
    const float* x         = (const float*)d_in[0];   // [50000, 256]
    const float* edge_attr = (const float*)d_in[1];   // [800000, 96]
    const float* u         = (const float*)d_in[2];   // [8, 64]
    const float* W1        = (const float*)d_in[3];   // [608, 1024]
    const float* b1        = (const float*)d_in[4];   // [1024]
    const float* W2        = (const float*)d_in[5];   // [1024, 256]
    const float* b2        = (const float*)d_in[6];   // [256]
    const int*   edge_index= (const int*)d_in[7];     // [2, 800000]
    const int*   batch     = (const int*)d_in[8];     // [50000]
    float* out = (float*)d_out;                       // [50000, 256]

    const int* col = edge_index + N_EDGES;

    __nv_bfloat16 *pHh, *pHl, *pMh, *pMl, *pW1h, *pW1l, *pW2h, *pW2l;
    cudaGetSymbolAddress((void**)&pHh,  g_Hh);
    cudaGetSymbolAddress((void**)&pHl,  g_Hl);
    cudaGetSymbolAddress((void**)&pMh,  g_midh);
    cudaGetSymbolAddress((void**)&pMl,  g_midl);
    cudaGetSymbolAddress((void**)&pW1h, g_Wt1h);
    cudaGetSymbolAddress((void**)&pW1l, g_Wt1l);
    cudaGetSymbolAddress((void**)&pW2h, g_Wt2h);
    cudaGetSymbolAddress((void**)&pW2l, g_Wt2l);

    const int SMEM_BYTES = 3 * 4 * 128 * 64;   // 98304
    cudaFuncSetAttribute(hmma_gemm_kernel<K1PAD, HIDDEN, 0>,
                         cudaFuncAttributeMaxDynamicSharedMemorySize, SMEM_BYTES);
    cudaFuncSetAttribute(hmma_gemm_kernel<HIDDEN, NODE_F, 1>,
                         cudaFuncAttributeMaxDynamicSharedMemorySize, SMEM_BYTES);

    // --- CSR build + gather reduction ---
    zero_deg_kernel<<<(N_NODES + 255) / 256, 256>>>();
    count_kernel<<<(N_EDGES + 255) / 256, 256>>>(col);
    scan_kernel<<<1, 1024>>>();
    fill_kernel<<<(N_EDGES + 255) / 256, 256>>>(col);
    gather_kernel<<<(N_NODES * 32 + 255) / 256, 256>>>(edge_attr);

    // --- independent prep ---
    wt1_kernel<<<(HIDDEN * K1PAD + 255) / 256, 256>>>(W1);
    wt2_kernel<<<(NODE_F * HIDDEN + 255) / 256, 256>>>(W2);
    {
        const int COLS = NODE_F + GLOB_F + (K1PAD - MLP_IN);
        long long total = (long long)N_NODES * COLS;
        rest_kernel<<<(int)((total + 255) / 256), 256>>>(x, u, batch);
    }

    // GEMM1: mid = relu(H @ W1 + b1)  [50000,1024]
    {
        dim3 grid(HIDDEN / 128, (N_NODES + 127) / 128);
        hmma_gemm_kernel<K1PAD, HIDDEN, 0><<<grid, 256, SMEM_BYTES>>>(
            pHh, pHl, pW1h, pW1l, b1, nullptr, pMh, pMl, nullptr, N_NODES);
    }
    // GEMM2: out = mid @ W2 + b2 + x  [50000,256]
    {
        dim3 grid(NODE_F / 128, (N_NODES + 127) / 128);
        hmma_gemm_kernel<HIDDEN, NODE_F, 1><<<grid, 256, SMEM_BYTES>>>(
            pMh, pMl, pW2h, pW2l, b2, x, nullptr, nullptr, out, N_NODES);
    }
}

// round 9
// speedup vs baseline: 2.7695x; 1.1142x over previous
#include <cuda_runtime.h>
#include <cuda_bf16.h>
#include <stdint.h>

#define N_NODES 50000
#define N_EDGES 800000
#define EDGE_F  96
#define NODE_F  256
#define GLOB_F  64
#define HIDDEN  1024
#define MLP_IN  608
#define KH      544   // GEMM1 K: x(256) + sum/max/mean(288); u folded into bias table

// ---------------- scratch (device globals: allocation-free) ----------------
__device__ int g_deg[N_NODES];        // zero at load; fill_kernel re-zeros each run
__device__ int g_off[N_NODES + 1];
__device__ int g_cur[N_NODES];
__device__ int g_bin[N_EDGES];
__device__ float g_ub1[8 * HIDDEN];   // per-graph bias table b1 + u[g] @ W1[544:608]
// split-bf16 operands
__device__ alignas(16) __nv_bfloat16 g_Hh[(size_t)N_NODES * KH];
__device__ alignas(16) __nv_bfloat16 g_Hl[(size_t)N_NODES * KH];
__device__ alignas(16) __nv_bfloat16 g_midh[(size_t)N_NODES * HIDDEN];
__device__ alignas(16) __nv_bfloat16 g_midl[(size_t)N_NODES * HIDDEN];
__device__ alignas(16) __nv_bfloat16 g_Wt1h[(size_t)HIDDEN * KH];
__device__ alignas(16) __nv_bfloat16 g_Wt1l[(size_t)HIDDEN * KH];
__device__ alignas(16) __nv_bfloat16 g_Wt2h[(size_t)NODE_F * HIDDEN];
__device__ alignas(16) __nv_bfloat16 g_Wt2l[(size_t)NODE_F * HIDDEN];

// ======================= helpers ===========================================
__device__ __forceinline__ uint32_t smem_to_u32(const void* p) {
    uint32_t a;
    asm("{ .reg .u64 t; cvta.to.shared.u64 t, %1; cvt.u32.u64 %0, t; }"
        : "=r"(a) : "l"(p));
    return a;
}

__device__ __forceinline__ void cp16(uint32_t dst, const void* src, bool valid) {
    asm volatile("cp.async.cg.shared.global [%0], [%1], 16, %2;"
                 :: "r"(dst), "l"(src), "r"(valid ? 16 : 0));
}
#define CP_COMMIT() asm volatile("cp.async.commit_group;" ::: "memory")
#define CP_WAIT(n)  asm volatile("cp.async.wait_group %0;" :: "n"(n) : "memory")

__device__ __forceinline__ void ldsm4(uint32_t* r, uint32_t addr) {
    asm volatile("ldmatrix.sync.aligned.m8n8.x4.shared.b16 {%0,%1,%2,%3}, [%4];"
                 : "=r"(r[0]), "=r"(r[1]), "=r"(r[2]), "=r"(r[3]) : "r"(addr));
}

__device__ __forceinline__ void mma16816(float* d, const uint32_t* a,
                                         uint32_t b0, uint32_t b1) {
    asm volatile(
        "mma.sync.aligned.m16n8k16.row.col.f32.bf16.bf16.f32 "
        "{%0,%1,%2,%3}, {%4,%5,%6,%7}, {%8,%9}, {%0,%1,%2,%3};"
        : "+f"(d[0]), "+f"(d[1]), "+f"(d[2]), "+f"(d[3])
        : "r"(a[0]), "r"(a[1]), "r"(a[2]), "r"(a[3]), "r"(b0), "r"(b1));
}

__device__ __forceinline__ void split_f32(float v, __nv_bfloat16& h, __nv_bfloat16& l) {
    h = __float2bfloat16(v);
    l = __float2bfloat16(v - __bfloat162float(h));
}

// 64B-row smem tile with XOR swizzle (conflict-free for 8-lane ldmatrix phases)
__device__ __forceinline__ uint32_t sw_off(int row, int chunk) {
    return (uint32_t)row * 64u + (uint32_t)((chunk ^ ((row >> 1) & 3)) << 4);
}

// ===================== CSR build ===========================================
__global__ void count_kernel(const int* __restrict__ col) {
    int e = blockIdx.x * blockDim.x + threadIdx.x;
    if (e < N_EDGES) atomicAdd(&g_deg[col[e]], 1);
}

// single-CTA chunked exclusive scan over g_deg -> g_off, g_cur
__global__ void scan_kernel() {
    __shared__ int warp_sums[32];
    __shared__ int carry_s;
    const int tid = threadIdx.x;
    const int lane = tid & 31, wid = tid >> 5;
    if (tid == 0) carry_s = 0;
    __syncthreads();
    for (int base = 0; base < N_NODES; base += 1024) {
        int i = base + tid;
        int v = (i < N_NODES) ? g_deg[i] : 0;
        int x = v;
        #pragma unroll
        for (int o = 1; o < 32; o <<= 1) {
            int y = __shfl_up_sync(0xFFFFFFFFu, x, o);
            if (lane >= o) x += y;
        }
        if (lane == 31) warp_sums[wid] = x;
        __syncthreads();
        if (wid == 0) {
            int w = warp_sums[lane];
            #pragma unroll
            for (int o = 1; o < 32; o <<= 1) {
                int y = __shfl_up_sync(0xFFFFFFFFu, w, o);
                if (lane >= o) w += y;
            }
            warp_sums[lane] = w;
        }
        __syncthreads();
        int excl = x - v + (wid > 0 ? warp_sums[wid - 1] : 0) + carry_s;
        if (i < N_NODES) {
            g_off[i] = excl;
            g_cur[i] = excl;
        }
        __syncthreads();
        if (tid == 0) carry_s += warp_sums[31];
        __syncthreads();
    }
    if (tid == 0) g_off[N_NODES] = N_EDGES;
}

// fill bins; also re-zero g_deg so the next replay starts clean (deterministic)
__global__ void fill_kernel(const int* __restrict__ col) {
    int e = blockIdx.x * blockDim.x + threadIdx.x;
    if (e < N_EDGES) {
        int pos = atomicAdd(&g_cur[col[e]], 1);
        g_bin[pos] = e;
    }
    if (e < N_NODES) g_deg[e] = 0;
}

// ============ merged prep: gather | rest(x) | wt1 | wt2 | ub1 ==============
// block-range dispatch; all sections independent, DRAM-bound, run concurrently.
#define G_GATHER 6250                         // 50000 warps, 8/block
#define G_REST   12500                        // 50000*256/4 threads /256
#define G_WT1    (HIDDEN * (KH / 4) / 256)    // 544
#define G_WT2    (NODE_F * (HIDDEN / 4) / 256)// 256
#define G_UB1    32                           // 8*1024 threads /256

__global__ void prep_kernel(const float* __restrict__ edge_attr,
                            const float* __restrict__ x,
                            const float* __restrict__ u,
                            const float* __restrict__ W1,
                            const float* __restrict__ b1,
                            const float* __restrict__ W2) {
    const int b = blockIdx.x;
    if (b < G_GATHER) {
        // ---- gather: warp per node, sum/max/mean -> H cols [256,544) ----
        const int warp_g = (b * 256 + (int)threadIdx.x) >> 5;
        if (warp_g >= N_NODES) return;
        const int lane = threadIdx.x & 31;
        const int beg = g_off[warp_g];
        const int end = g_off[warp_g + 1];

        float s0 = 0.f, s1 = 0.f, s2 = 0.f;
        float m0 = -__int_as_float(0x7F800000), m1 = m0, m2 = m0;

        for (int i = beg; i < end; i++) {
            const int e = g_bin[i];
            const float* row = edge_attr + (size_t)e * EDGE_F;
            float v0 = row[lane];
            float v1 = row[lane + 32];
            float v2 = row[lane + 64];
            s0 += v0; s1 += v1; s2 += v2;
            m0 = fmaxf(m0, v0); m1 = fmaxf(m1, v1); m2 = fmaxf(m2, v2);
        }
        const int cnt = end - beg;
        if (cnt == 0) { m0 = 0.f; m1 = 0.f; m2 = 0.f; }
        const float inv = 1.0f / (float)max(cnt, 1);

        const size_t rb = (size_t)warp_g * KH;
        __nv_bfloat16 h, l;
        split_f32(s0, h, l); g_Hh[rb + 256 + lane] = h; g_Hl[rb + 256 + lane] = l;
        split_f32(s1, h, l); g_Hh[rb + 288 + lane] = h; g_Hl[rb + 288 + lane] = l;
        split_f32(s2, h, l); g_Hh[rb + 320 + lane] = h; g_Hl[rb + 320 + lane] = l;
        split_f32(m0, h, l); g_Hh[rb + 352 + lane] = h; g_Hl[rb + 352 + lane] = l;
        split_f32(m1, h, l); g_Hh[rb + 384 + lane] = h; g_Hl[rb + 384 + lane] = l;
        split_f32(m2, h, l); g_Hh[rb + 416 + lane] = h; g_Hl[rb + 416 + lane] = l;
        split_f32(s0 * inv, h, l); g_Hh[rb + 448 + lane] = h; g_Hl[rb + 448 + lane] = l;
        split_f32(s1 * inv, h, l); g_Hh[rb + 480 + lane] = h; g_Hl[rb + 480 + lane] = l;
        split_f32(s2 * inv, h, l); g_Hh[rb + 512 + lane] = h; g_Hl[rb + 512 + lane] = l;
    } else if (b < G_GATHER + G_REST) {
        // ---- rest: H cols [0,256) = x, vectorized x4 ----
        const int t = (b - G_GATHER) * 256 + (int)threadIdx.x;
        const int n = t >> 6;            // /64
        const int c = (t & 63) * 4;
        if (n >= N_NODES) return;
        const float4 v = *reinterpret_cast<const float4*>(x + (size_t)n * NODE_F + c);
        const size_t o = (size_t)n * KH + c;
        __nv_bfloat16 h0, l0, h1, l1, h2, l2, h3, l3;
        split_f32(v.x, h0, l0); split_f32(v.y, h1, l1);
        split_f32(v.z, h2, l2); split_f32(v.w, h3, l3);
        __nv_bfloat162 ph0(h0, h1), ph1(h2, h3), pl0(l0, l1), pl1(l2, l3);
        reinterpret_cast<__nv_bfloat162*>(g_Hh + o)[0] = ph0;
        reinterpret_cast<__nv_bfloat162*>(g_Hh + o)[1] = ph1;
        reinterpret_cast<__nv_bfloat162*>(g_Hl + o)[0] = pl0;
        reinterpret_cast<__nv_bfloat162*>(g_Hl + o)[1] = pl1;
    } else if (b < G_GATHER + G_REST + G_WT1) {
        // ---- wt1: Wt1[n][k] = W1[k][n], k in [0,544), x4 along k ----
        const int t = (b - G_GATHER - G_REST) * 256 + (int)threadIdx.x;
        const int n = t / (KH / 4);
        const int k = (t % (KH / 4)) * 4;
        __nv_bfloat16 h, l;
        const size_t o = (size_t)n * KH + k;
        #pragma unroll
        for (int i = 0; i < 4; i++) {
            split_f32(W1[(size_t)(k + i) * HIDDEN + n], h, l);
            g_Wt1h[o + i] = h;
            g_Wt1l[o + i] = l;
        }
    } else if (b < G_GATHER + G_REST + G_WT1 + G_WT2) {
        // ---- wt2: Wt2[n][k] = W2[k][n], k in [0,1024), x4 ----
        const int t = (b - G_GATHER - G_REST - G_WT1) * 256 + (int)threadIdx.x;
        const int n = t / (HIDDEN / 4);
        const int k = (t % (HIDDEN / 4)) * 4;
        __nv_bfloat16 h, l;
        const size_t o = (size_t)n * HIDDEN + k;
        #pragma unroll
        for (int i = 0; i < 4; i++) {
            split_f32(W2[(size_t)(k + i) * NODE_F + n], h, l);
            g_Wt2h[o + i] = h;
            g_Wt2l[o + i] = l;
        }
    } else {
        // ---- ub1[g][n] = b1[n] + sum_k u[g,k] * W1[544+k][n] ----
        const int t = (b - G_GATHER - G_REST - G_WT1 - G_WT2) * 256 + (int)threadIdx.x;
        const int g = t >> 10;
        const int n = t & 1023;
        if (g >= 8) return;
        float s = b1[n];
        #pragma unroll 8
        for (int k = 0; k < GLOB_F; k++)
            s = fmaf(u[g * GLOB_F + k], W1[(size_t)(KH + k) * HIDDEN + n], s);
        g_ub1[g * HIDDEN + n] = s;
    }
}

// ================= split-bf16 GEMM on mma.sync (HMMA) ======================
// C[128,128]/CTA, 8 warps 2(M)x4(N), warp tile 64x32, S=3 stages, 2 CTAs/SM.
// acc += Ah*Bh + Ah*Bl + Al*Bh
// MODE 0: out = relu(acc + ub1[batch[row]][col]) -> bf16 hi/lo
// MODE 1: out = acc + bias[col] + resid -> f32
template<int K_TOTAL, int N_TOTAL, int MODE>
__global__ void __launch_bounds__(256, 2) hmma_gemm_kernel(
    const __nv_bfloat16* __restrict__ Ah, const __nv_bfloat16* __restrict__ Al,
    const __nv_bfloat16* __restrict__ Bh, const __nv_bfloat16* __restrict__ Bl,
    const float* __restrict__ bias, const float* __restrict__ resid,
    const int* __restrict__ batchp,
    __nv_bfloat16* __restrict__ outh, __nv_bfloat16* __restrict__ outl,
    float* __restrict__ outf, int M)
{
    constexpr int KC = 32;
    constexpr int S  = 3;
    constexpr int TILE_B = 128 * 64;
    constexpr int STAGE_B = 4 * TILE_B;
    constexpr int NCH = K_TOTAL / KC;

    extern __shared__ char smem[];
    const uint32_t smem_u = smem_to_u32(smem);

    const int tid = threadIdx.x;
    const int lid = tid & 31;
    const int wid = tid >> 5;
    const int warp_m = wid & 1;
    const int warp_n = wid >> 1;
    const int blockN = blockIdx.x * 128;
    const int blockM = blockIdx.y * 128;

    float acc[64];
    #pragma unroll
    for (int i = 0; i < 64; i++) acc[i] = 0.0f;

    const int ldrow0 = tid >> 2;
    const int ldseg  = tid & 3;

    auto load_chunk = [&](int c) {
        if (c >= NCH) return;
        const int kb = c * KC;
        const uint32_t sb = smem_u + (uint32_t)(c % S) * STAGE_B;
        #pragma unroll
        for (int i = 0; i < 2; i++) {
            const int row = ldrow0 + 64 * i;
            const uint32_t doff = sw_off(row, ldseg);
            const int gr = blockM + row;
            const bool v = gr < M;
            const size_t goA = (size_t)(v ? gr : 0) * K_TOTAL + kb + ldseg * 8;
            cp16(sb + 0 * TILE_B + doff, Ah + goA, v);
            cp16(sb + 1 * TILE_B + doff, Al + goA, v);
            const size_t goB = (size_t)(blockN + row) * K_TOTAL + kb + ldseg * 8;
            cp16(sb + 2 * TILE_B + doff, Bh + goB, true);
            cp16(sb + 3 * TILE_B + doff, Bl + goB, true);
        }
    };

    #pragma unroll
    for (int c = 0; c < S - 1; c++) {
        load_chunk(c);
        CP_COMMIT();
    }

    const int lr = lid & 15;
    const int lk = (lid >> 4) * 8;

    for (int c = 0; c < NCH; c++) {
        load_chunk(c + S - 1);
        CP_COMMIT();
        CP_WAIT(S - 1);
        __syncthreads();

        const uint32_t sb = smem_u + (uint32_t)(c % S) * STAGE_B;
        const uint32_t aH = sb, aL = sb + TILE_B;
        const uint32_t bH = sb + 2 * TILE_B, bL = sb + 3 * TILE_B;

        #pragma unroll
        for (int kk = 0; kk < KC; kk += 16) {
            const int kchunk = (kk + lk) >> 3;
            uint32_t bh[8], bl[8];
            #pragma unroll
            for (int bn = 0; bn < 2; bn++) {
                const uint32_t off = sw_off(warp_n * 32 + bn * 16 + lr, kchunk);
                ldsm4(&bh[bn * 4], bH + off);
                ldsm4(&bl[bn * 4], bL + off);
            }
            #pragma unroll
            for (int am = 0; am < 4; am++) {
                uint32_t ah[4], al[4];
                const uint32_t off = sw_off(warp_m * 64 + am * 16 + lr, kchunk);
                ldsm4(ah, aH + off);
                ldsm4(al, aL + off);
                #pragma unroll
                for (int an = 0; an < 4; an++) {
                    const int bn = an >> 1, sel = an & 1;
                    float* d = &acc[(am * 4 + an) * 4];
                    const uint32_t h0 = bh[bn * 4 + sel], h1 = bh[bn * 4 + sel + 2];
                    const uint32_t l0 = bl[bn * 4 + sel], l1 = bl[bn * 4 + sel + 2];
                    mma16816(d, ah, h0, h1);
                    mma16816(d, ah, l0, l1);
                    mma16816(d, al, h0, h1);
                }
            }
        }
        __syncthreads();
    }

    const int g = lid >> 2;
    const int t = lid & 3;
    #pragma unroll
    for (int am = 0; am < 4; am++) {
        #pragma unroll
        for (int an = 0; an < 4; an++) {
            const float* d = &acc[(am * 4 + an) * 4];
            const int col = blockN + warp_n * 32 + an * 8 + 2 * t;
            #pragma unroll
            for (int half = 0; half < 2; half++) {
                const int row = blockM + warp_m * 64 + am * 16 + g + half * 8;
                if (row >= M) continue;
                float bia0, bia1;
                if (MODE == 0) {
                    const int gg = batchp[row];
                    bia0 = bias[gg * N_TOTAL + col];
                    bia1 = bias[gg * N_TOTAL + col + 1];
                } else {
                    bia0 = bias[col];
                    bia1 = bias[col + 1];
                }
                float v0 = d[half * 2 + 0] + bia0;
                float v1 = d[half * 2 + 1] + bia1;
                const size_t o = (size_t)row * N_TOTAL + col;
                if (MODE == 0) {
                    v0 = fmaxf(v0, 0.0f);
                    v1 = fmaxf(v1, 0.0f);
                    __nv_bfloat16 h0, l0, h1, l1;
                    split_f32(v0, h0, l0);
                    split_f32(v1, h1, l1);
                    __nv_bfloat162 ph = __nv_bfloat162(h0, h1);
                    __nv_bfloat162 pl = __nv_bfloat162(l0, l1);
                    *reinterpret_cast<uint32_t*>(outh + o) = *reinterpret_cast<uint32_t*>(&ph);
                    *reinterpret_cast<uint32_t*>(outl + o) = *reinterpret_cast<uint32_t*>(&pl);
                } else {
                    float2 r;
                    r.x = v0 + resid[o];
                    r.y = v1 + resid[o + 1];
                    *reinterpret_cast<float2*>(outf + o) = r;
                }
            }
        }
    }
}

// ---------------- launch ----------------
extern "C" void kernel_launch(void* const* d_in, const int* in_sizes, int n_in,
                              void* d_out, int out_size) {
    const float* x         = (const float*)d_in[0];
    const float* edge_attr = (const float*)d_in[1];
    const float* u         = (const float*)d_in[2];
    const float* W1        = (const float*)d_in[3];
    const float* b1        = (const float*)d_in[4];
    const float* W2        = (const float*)d_in[5];
    const float* b2        = (const float*)d_in[6];
    const int*   edge_index= (const int*)d_in[7];
    const int*   batch     = (const int*)d_in[8];
    float* out = (float*)d_out;

    const int* col = edge_index + N_EDGES;

    __nv_bfloat16 *pHh, *pHl, *pMh, *pMl, *pW1h, *pW1l, *pW2h, *pW2l;
    float* pUb1;
    cudaGetSymbolAddress((void**)&pHh,  g_Hh);
    cudaGetSymbolAddress((void**)&pHl,  g_Hl);
    cudaGetSymbolAddress((void**)&pMh,  g_midh);
    cudaGetSymbolAddress((void**)&pMl,  g_midl);
    cudaGetSymbolAddress((void**)&pW1h, g_Wt1h);
    cudaGetSymbolAddress((void**)&pW1l, g_Wt1l);
    cudaGetSymbolAddress((void**)&pW2h, g_Wt2h);
    cudaGetSymbolAddress((void**)&pW2l, g_Wt2l);
    cudaGetSymbolAddress((void**)&pUb1, g_ub1);

    const int SMEM_BYTES = 3 * 4 * 128 * 64;   // 98304
    cudaFuncSetAttribute(hmma_gemm_kernel<KH, HIDDEN, 0>,
                         cudaFuncAttributeMaxDynamicSharedMemorySize, SMEM_BYTES);
    cudaFuncSetAttribute(hmma_gemm_kernel<HIDDEN, NODE_F, 1>,
                         cudaFuncAttributeMaxDynamicSharedMemorySize, SMEM_BYTES);

    // 1) CSR: count (g_deg zeroed by previous run / static init)
    count_kernel<<<(N_EDGES + 255) / 256, 256>>>(col);
    // 2) scan
    scan_kernel<<<1, 1024>>>();
    // 3) fill (+ re-zero g_deg for next replay)
    fill_kernel<<<(N_EDGES + 255) / 256, 256>>>(col);
    // 4) merged prep: gather | x-copy | wt1 | wt2 | ub1
    prep_kernel<<<G_GATHER + G_REST + G_WT1 + G_WT2 + G_UB1, 256>>>(
        edge_attr, x, u, W1, b1, W2);
    // 5) GEMM1: mid = relu(H @ W1[0:544] + ub1[batch])  [50000,1024]
    {
        dim3 grid(HIDDEN / 128, (N_NODES + 127) / 128);
        hmma_gemm_kernel<KH, HIDDEN, 0><<<grid, 256, SMEM_BYTES>>>(
            pHh, pHl, pW1h, pW1l, pUb1, nullptr, batch, pMh, pMl, nullptr, N_NODES);
    }
    // 6) GEMM2: out = mid @ W2 + b2 + x  [50000,256]
    {
        dim3 grid(NODE_F / 128, (N_NODES + 127) / 128);
        hmma_gemm_kernel<HIDDEN, NODE_F, 1><<<grid, 256, SMEM_BYTES>>>(
            pMh, pMl, pW2h, pW2l, b2, x, nullptr, nullptr, nullptr, out, N_NODES);
    }
}